// round 10
// baseline (speedup 1.0000x reference)
#include <cuda_runtime.h>
#include <stdint.h>

// kNN: B=2, N=2048, D=16, K=16. Output (B,N,K,2) FLOAT32: [b, idx].
//
// transpose_kernel: AoS points -> SoA float4 scratch (coalesced loads).
// knn_kernel: TWO WARPS PER QUERY (each scans 1024 candidates, 32 steps),
// per-lane sorted top-4 branchy insert (stable strict-<, ties -> lower index
// = jax.lax.top_k), 16-round warp-min pop merge (64-bit keys
// dist_bits<<32|idx). Round-r winner captured by lane r. Warp pair combines
// its two sorted 16-lists via a 5-stage bitonic merge; even warp writes out.
// Guard: lane popping all 4 -> exact depth-16 SMEM fallback (P ~ 3e-3/warp).

#define NPTS 2048
#define KNN  16
#define KL   4
#define WPC  8                     // 8 warps = 4 queries per CTA
#define THREADS (WPC * 32)
#define HALF_STEPS 32              // 1024 candidates / 32 lanes

__device__ float4 T4g[2][4][NPTS];   // 256 KB static scratch

__global__ void transpose_kernel(const float* __restrict__ points)
{
    int idx = blockIdx.x * blockDim.x + threadIdx.x;   // b*8192 + c*2048 + j
    if (idx >= 2 * 4 * NPTS) return;
    int j = idx & (NPTS - 1);
    int c = (idx >> 11) & 3;
    int b = idx >> 13;
    const float4* P4 = reinterpret_cast<const float4*>(points);
    T4g[b][c][j] = P4[(b * NPTS + j) * 4 + c];
}

__device__ __forceinline__ unsigned dist_key(
    float4 q0, float4 q1, float4 q2, float4 q3,
    float4 a0, float4 a1, float4 a2, float4 a3)
{
    float s = 0.0f, d;
    d = q0.x - a0.x; s = fmaf(d, d, s);
    d = q0.y - a0.y; s = fmaf(d, d, s);
    d = q0.z - a0.z; s = fmaf(d, d, s);
    d = q0.w - a0.w; s = fmaf(d, d, s);
    d = q1.x - a1.x; s = fmaf(d, d, s);
    d = q1.y - a1.y; s = fmaf(d, d, s);
    d = q1.z - a1.z; s = fmaf(d, d, s);
    d = q1.w - a1.w; s = fmaf(d, d, s);
    d = q2.x - a2.x; s = fmaf(d, d, s);
    d = q2.y - a2.y; s = fmaf(d, d, s);
    d = q2.z - a2.z; s = fmaf(d, d, s);
    d = q2.w - a2.w; s = fmaf(d, d, s);
    d = q3.x - a3.x; s = fmaf(d, d, s);
    d = q3.y - a3.y; s = fmaf(d, d, s);
    d = q3.z - a3.z; s = fmaf(d, d, s);
    d = q3.w - a3.w; s = fmaf(d, d, s);
    return __float_as_uint(__fsqrt_rn(s));   // compare post-sqrt (ref semantics)
}

__device__ __forceinline__ unsigned long long umin64(unsigned long long a,
                                                     unsigned long long b)
{ return (b < a) ? b : a; }
__device__ __forceinline__ unsigned long long umax64(unsigned long long a,
                                                     unsigned long long b)
{ return (a < b) ? b : a; }

__global__ void knn_kernel(float2* __restrict__ out)
{
    __shared__ unsigned sD[WPC][KNN][32];            // fallback scratch (rare)
    __shared__ int      sJ[WPC][KNN][32];
    __shared__ unsigned long long sX[WPC][16];       // pair exchange

    const int b    = blockIdx.y;
    const int wid  = threadIdx.x >> 5;
    const int lane = threadIdx.x & 31;
    const int pair = wid >> 1;
    const int half = wid & 1;
    const int q    = blockIdx.x * 4 + pair;          // 0..2047
    const int jbase = half * (NPTS / 2);             // this warp's candidate half

    const float4 q0 = T4g[b][0][q];
    const float4 q1 = T4g[b][1][q];
    const float4 q2 = T4g[b][2][q];
    const float4 q3 = T4g[b][3][q];

    // ---- Pass over 1024 candidates: per-lane sorted top-4 (branchy, proven) ----
    unsigned D[KL];
    int      J[KL];
#pragma unroll
    for (int i = 0; i < KL; ++i) { D[i] = 0xFFFFFFFFu; J[i] = 0x7FFFFFFF; }

#pragma unroll 2
    for (int t = 0; t < HALF_STEPS; ++t) {
        const int j = jbase + t * 32 + lane;
        float4 a0 = T4g[b][0][j];
        float4 a1 = T4g[b][1][j];
        float4 a2 = T4g[b][2][j];
        float4 a3 = T4g[b][3][j];
        unsigned kb = dist_key(q0, q1, q2, q3, a0, a1, a2, a3);
        if (j == q) kb = 0xFFFFFFFFu;                // exclude self

        if (kb < D[KL - 1]) {                        // stable strict-<
            D[KL - 1] = kb; J[KL - 1] = j;
#pragma unroll
            for (int i = KL - 1; i > 0; --i) {
                if (D[i] < D[i - 1]) {
                    unsigned td = D[i]; D[i] = D[i - 1]; D[i - 1] = td;
                    int      tj = J[i]; J[i] = J[i - 1]; J[i - 1] = tj;
                }
            }
        }
    }

    // ---- 16-round warp-min pop merge; lane r captures round-r winner ----
    unsigned long long keep = 0xFFFFFFFFFFFFFFFFull;
    int cnt = 0;
    unsigned long long h = ((unsigned long long)D[0] << 32) | (unsigned)J[0];
#pragma unroll
    for (int r = 0; r < KNN; ++r) {
        unsigned long long v = h;
#pragma unroll
        for (int off = 16; off > 0; off >>= 1)
            v = umin64(v, __shfl_xor_sync(0xFFFFFFFFu, v, off));
        if (lane == r) keep = v;
        if (h == v) {                                // real keys unique
            ++cnt;
#pragma unroll
            for (int i = 0; i < KL - 1; ++i) { D[i] = D[i + 1]; J[i] = J[i + 1]; }
            D[KL - 1] = 0xFFFFFFFFu; J[KL - 1] = 0x7FFFFFFF;
            h = ((unsigned long long)D[0] << 32) | (unsigned)J[0];
        }
    }

    // ---- Guard: fully-popped lane may have discarded a needed 5th entry ----
    if (__ballot_sync(0xFFFFFFFFu, cnt == KL) != 0) {
#pragma unroll 1
        for (int i = 0; i < KNN; ++i) { sD[wid][i][lane] = 0xFFFFFFFFu; sJ[wid][i][lane] = 0x7FFFFFFF; }
#pragma unroll 1
        for (int t = 0; t < HALF_STEPS; ++t) {
            const int j = jbase + t * 32 + lane;
            float4 a0 = T4g[b][0][j], a1 = T4g[b][1][j],
                   a2 = T4g[b][2][j], a3 = T4g[b][3][j];
            unsigned kk = dist_key(q0, q1, q2, q3, a0, a1, a2, a3);
            if (j == q) continue;
            if (kk < sD[wid][KNN - 1][lane]) {
                int p = KNN - 1;
#pragma unroll 1
                while (p > 0 && kk < sD[wid][p - 1][lane]) {
                    sD[wid][p][lane] = sD[wid][p - 1][lane];
                    sJ[wid][p][lane] = sJ[wid][p - 1][lane];
                    --p;
                }
                sD[wid][p][lane] = kk; sJ[wid][p][lane] = j;
            }
        }
        int cur = 0;
        unsigned long long h2 = ((unsigned long long)sD[wid][0][lane] << 32)
                              | (unsigned)sJ[wid][0][lane];
#pragma unroll 1
        for (int r = 0; r < KNN; ++r) {
            unsigned long long v = h2;
#pragma unroll
            for (int off = 16; off > 0; off >>= 1)
                v = umin64(v, __shfl_xor_sync(0xFFFFFFFFu, v, off));
            if (lane == r) keep = v;
            if (h2 == v) {
                ++cur;
                h2 = (cur < KNN)
                   ? (((unsigned long long)sD[wid][cur][lane] << 32) | (unsigned)sJ[wid][cur][lane])
                   : 0xFFFFFFFFFFFFFFFFull;
            }
        }
    }

    // ---- Exchange + cross-half bitonic merge (even warp of each pair) ----
    if (lane < 16) sX[wid][lane] = keep;
    __syncthreads();

    if (half == 0) {
        // lanes 0..15: own ascending list; lanes 16..31: partner reversed.
        unsigned long long X = (lane < 16) ? keep : sX[wid + 1][31 - lane];
        // Bitonic merge (asc): ascending ++ descending input.
#pragma unroll
        for (int off = 16; off > 0; off >>= 1) {
            unsigned long long o = __shfl_xor_sync(0xFFFFFFFFu, X, off);
            X = (lane & off) ? umax64(X, o) : umin64(X, o);
        }
        if (lane < 16) {
            float2* outp = out + ((size_t)b * NPTS + q) * KNN;
            outp[lane] = make_float2((float)b,
                                     (float)(int)(unsigned)(X & 0xFFFFFFFFull));
        }
    }
}

extern "C" void kernel_launch(void* const* d_in, const int* in_sizes, int n_in,
                              void* d_out, int out_size)
{
    // points (2*2048*16) is the SMALLER input (features is 4x larger).
    const float* points;
    if (n_in >= 2) {
        points = (in_sizes[0] <= in_sizes[1]) ? (const float*)d_in[0]
                                              : (const float*)d_in[1];
    } else {
        points = (const float*)d_in[0];
    }

    transpose_kernel<<<(2 * 4 * NPTS + 255) / 256, 256>>>(points);

    dim3 grid(NPTS / 4, 2);          // 4 queries per CTA (8 warps), 1024 CTAs
    knn_kernel<<<grid, THREADS>>>((float2*)d_out);
}

// round 11
// speedup vs baseline: 1.7646x; 1.7646x over previous
#include <cuda_runtime.h>
#include <stdint.h>

// kNN: B=2, N=2048, D=16, K=16. Output (B,N,K,2) FLOAT32: [b, idx].
//
// R9 architecture (best: 45.8us) with KL=8 -> 6 (recomputed-safe guard).
// transpose_kernel: AoS points -> SoA float4 scratch (coalesced loads).
// knn_kernel: TWO WARPS PER QUERY (each scans 1024 candidates, 32 steps),
// per-lane sorted top-6 branchy insert (stable strict-<, ties -> lower index
// = jax.lax.top_k), 16-round warp-min pop merge (64-bit keys
// dist_bits<<32|idx). Round-r winner captured by lane r. Warp pair combines
// its two sorted 16-lists via a 5-stage bitonic merge; even warp writes out.
// Guard: lane popping all 6 -> exact depth-16 SMEM fallback
// (P ~= 32*P(Bin(16,1/32)>=6) ~= 1.7e-4/warp => ~1.4 warps/launch).

#define NPTS 2048
#define KNN  16
#define KL   6
#define WPC  8                     // 8 warps = 4 queries per CTA
#define THREADS (WPC * 32)
#define HALF_STEPS 32              // 1024 candidates / 32 lanes

__device__ float4 T4g[2][4][NPTS];   // 256 KB static scratch

__global__ void transpose_kernel(const float* __restrict__ points)
{
    int idx = blockIdx.x * blockDim.x + threadIdx.x;   // b*8192 + c*2048 + j
    if (idx >= 2 * 4 * NPTS) return;
    int j = idx & (NPTS - 1);
    int c = (idx >> 11) & 3;
    int b = idx >> 13;
    const float4* P4 = reinterpret_cast<const float4*>(points);
    T4g[b][c][j] = P4[(b * NPTS + j) * 4 + c];
}

__device__ __forceinline__ unsigned dist_key(
    float4 q0, float4 q1, float4 q2, float4 q3,
    float4 a0, float4 a1, float4 a2, float4 a3)
{
    float s = 0.0f, d;
    d = q0.x - a0.x; s = fmaf(d, d, s);
    d = q0.y - a0.y; s = fmaf(d, d, s);
    d = q0.z - a0.z; s = fmaf(d, d, s);
    d = q0.w - a0.w; s = fmaf(d, d, s);
    d = q1.x - a1.x; s = fmaf(d, d, s);
    d = q1.y - a1.y; s = fmaf(d, d, s);
    d = q1.z - a1.z; s = fmaf(d, d, s);
    d = q1.w - a1.w; s = fmaf(d, d, s);
    d = q2.x - a2.x; s = fmaf(d, d, s);
    d = q2.y - a2.y; s = fmaf(d, d, s);
    d = q2.z - a2.z; s = fmaf(d, d, s);
    d = q2.w - a2.w; s = fmaf(d, d, s);
    d = q3.x - a3.x; s = fmaf(d, d, s);
    d = q3.y - a3.y; s = fmaf(d, d, s);
    d = q3.z - a3.z; s = fmaf(d, d, s);
    d = q3.w - a3.w; s = fmaf(d, d, s);
    return __float_as_uint(__fsqrt_rn(s));   // compare post-sqrt (ref semantics)
}

__device__ __forceinline__ unsigned long long umin64(unsigned long long a,
                                                     unsigned long long b)
{ return (b < a) ? b : a; }
__device__ __forceinline__ unsigned long long umax64(unsigned long long a,
                                                     unsigned long long b)
{ return (a < b) ? b : a; }

__global__ void knn_kernel(float2* __restrict__ out)
{
    __shared__ unsigned sD[WPC][KNN][32];            // fallback scratch (rare)
    __shared__ int      sJ[WPC][KNN][32];
    __shared__ unsigned long long sX[WPC][16];       // pair exchange

    const int b    = blockIdx.y;
    const int wid  = threadIdx.x >> 5;
    const int lane = threadIdx.x & 31;
    const int pair = wid >> 1;
    const int half = wid & 1;
    const int q    = blockIdx.x * 4 + pair;          // 0..2047
    const int jbase = half * (NPTS / 2);             // this warp's candidate half

    const float4 q0 = T4g[b][0][q];
    const float4 q1 = T4g[b][1][q];
    const float4 q2 = T4g[b][2][q];
    const float4 q3 = T4g[b][3][q];

    // ---- Pass over 1024 candidates: per-lane sorted top-6 (branchy, proven) ----
    unsigned D[KL];
    int      J[KL];
#pragma unroll
    for (int i = 0; i < KL; ++i) { D[i] = 0xFFFFFFFFu; J[i] = 0x7FFFFFFF; }

#pragma unroll 2
    for (int t = 0; t < HALF_STEPS; ++t) {
        const int j = jbase + t * 32 + lane;
        float4 a0 = T4g[b][0][j];
        float4 a1 = T4g[b][1][j];
        float4 a2 = T4g[b][2][j];
        float4 a3 = T4g[b][3][j];
        unsigned kb = dist_key(q0, q1, q2, q3, a0, a1, a2, a3);
        if (j == q) kb = 0xFFFFFFFFu;                // exclude self

        if (kb < D[KL - 1]) {                        // stable strict-<
            D[KL - 1] = kb; J[KL - 1] = j;
#pragma unroll
            for (int i = KL - 1; i > 0; --i) {
                if (D[i] < D[i - 1]) {
                    unsigned td = D[i]; D[i] = D[i - 1]; D[i - 1] = td;
                    int      tj = J[i]; J[i] = J[i - 1]; J[i - 1] = tj;
                }
            }
        }
    }

    // ---- 16-round warp-min pop merge; lane r captures round-r winner ----
    unsigned long long keep = 0xFFFFFFFFFFFFFFFFull;
    int cnt = 0;
    unsigned long long h = ((unsigned long long)D[0] << 32) | (unsigned)J[0];
#pragma unroll
    for (int r = 0; r < KNN; ++r) {
        unsigned long long v = h;
#pragma unroll
        for (int off = 16; off > 0; off >>= 1)
            v = umin64(v, __shfl_xor_sync(0xFFFFFFFFu, v, off));
        if (lane == r) keep = v;
        if (h == v) {                                // real keys unique
            ++cnt;
#pragma unroll
            for (int i = 0; i < KL - 1; ++i) { D[i] = D[i + 1]; J[i] = J[i + 1]; }
            D[KL - 1] = 0xFFFFFFFFu; J[KL - 1] = 0x7FFFFFFF;
            h = ((unsigned long long)D[0] << 32) | (unsigned)J[0];
        }
    }

    // ---- Guard: fully-popped lane may have discarded a needed 7th entry ----
    if (__ballot_sync(0xFFFFFFFFu, cnt == KL) != 0) {
#pragma unroll 1
        for (int i = 0; i < KNN; ++i) { sD[wid][i][lane] = 0xFFFFFFFFu; sJ[wid][i][lane] = 0x7FFFFFFF; }
#pragma unroll 1
        for (int t = 0; t < HALF_STEPS; ++t) {
            const int j = jbase + t * 32 + lane;
            float4 a0 = T4g[b][0][j], a1 = T4g[b][1][j],
                   a2 = T4g[b][2][j], a3 = T4g[b][3][j];
            unsigned kk = dist_key(q0, q1, q2, q3, a0, a1, a2, a3);
            if (j == q) continue;
            if (kk < sD[wid][KNN - 1][lane]) {
                int p = KNN - 1;
#pragma unroll 1
                while (p > 0 && kk < sD[wid][p - 1][lane]) {
                    sD[wid][p][lane] = sD[wid][p - 1][lane];
                    sJ[wid][p][lane] = sJ[wid][p - 1][lane];
                    --p;
                }
                sD[wid][p][lane] = kk; sJ[wid][p][lane] = j;
            }
        }
        int cur = 0;
        unsigned long long h2 = ((unsigned long long)sD[wid][0][lane] << 32)
                              | (unsigned)sJ[wid][0][lane];
#pragma unroll 1
        for (int r = 0; r < KNN; ++r) {
            unsigned long long v = h2;
#pragma unroll
            for (int off = 16; off > 0; off >>= 1)
                v = umin64(v, __shfl_xor_sync(0xFFFFFFFFu, v, off));
            if (lane == r) keep = v;
            if (h2 == v) {
                ++cur;
                h2 = (cur < KNN)
                   ? (((unsigned long long)sD[wid][cur][lane] << 32) | (unsigned)sJ[wid][cur][lane])
                   : 0xFFFFFFFFFFFFFFFFull;
            }
        }
    }

    // ---- Exchange + cross-half bitonic merge (even warp of each pair) ----
    if (lane < 16) sX[wid][lane] = keep;
    __syncthreads();

    if (half == 0) {
        // lanes 0..15: own ascending list; lanes 16..31: partner reversed.
        unsigned long long X = (lane < 16) ? keep : sX[wid + 1][31 - lane];
        // Bitonic merge (asc): ascending ++ descending input.
#pragma unroll
        for (int off = 16; off > 0; off >>= 1) {
            unsigned long long o = __shfl_xor_sync(0xFFFFFFFFu, X, off);
            X = (lane & off) ? umax64(X, o) : umin64(X, o);
        }
        if (lane < 16) {
            float2* outp = out + ((size_t)b * NPTS + q) * KNN;
            outp[lane] = make_float2((float)b,
                                     (float)(int)(unsigned)(X & 0xFFFFFFFFull));
        }
    }
}

extern "C" void kernel_launch(void* const* d_in, const int* in_sizes, int n_in,
                              void* d_out, int out_size)
{
    // points (2*2048*16) is the SMALLER input (features is 4x larger).
    const float* points;
    if (n_in >= 2) {
        points = (in_sizes[0] <= in_sizes[1]) ? (const float*)d_in[0]
                                              : (const float*)d_in[1];
    } else {
        points = (const float*)d_in[0];
    }

    transpose_kernel<<<(2 * 4 * NPTS + 255) / 256, 256>>>(points);

    dim3 grid(NPTS / 4, 2);          // 4 queries per CTA (8 warps), 1024 CTAs
    knn_kernel<<<grid, THREADS>>>((float2*)d_out);
}

// round 12
// speedup vs baseline: 1.8572x; 1.0525x over previous
#include <cuda_runtime.h>
#include <stdint.h>

// kNN: B=2, N=2048, D=16, K=16. Output (B,N,K,2) FLOAT32: [b, idx].
//
// R11 architecture (best 45.5us) + two changes:
//  1) Distance via packed f32x2 FMA (PTX fma.rn.f32x2 -> FFMA2): 16 packed
//     slots replace 32 scalar FADD/FFMA. Candidates loaded as ulonglong2.
//  2) 128-thread CTAs (WPC=4, 2 queries/CTA), __launch_bounds__(128,9):
//     9 CTAs/SM at 56 regs -> 36 resident warps (vs 32).
// Unchanged: per-lane sorted top-6 branchy insert (stable strict-<, ties ->
// lower index = jax.lax.top_k), 16-round warp-min pop merge over 64-bit keys
// (dist_bits<<32|idx), cross-half bitonic pair merge, exact depth-16 SMEM
// fallback guard (P ~ 1.7e-4/warp).

#define NPTS 2048
#define KNN  16
#define KL   6
#define WPC  4                     // 4 warps = 2 queries per CTA
#define THREADS (WPC * 32)
#define HALF_STEPS 32              // 1024 candidates / 32 lanes

__device__ float4 T4g[2][4][NPTS];   // 256 KB static scratch

__global__ void transpose_kernel(const float* __restrict__ points)
{
    int idx = blockIdx.x * blockDim.x + threadIdx.x;   // b*8192 + c*2048 + j
    if (idx >= 2 * 4 * NPTS) return;
    int j = idx & (NPTS - 1);
    int c = (idx >> 11) & 3;
    int b = idx >> 13;
    const float4* P4 = reinterpret_cast<const float4*>(points);
    T4g[b][c][j] = P4[(b * NPTS + j) * 4 + c];
}

__device__ __forceinline__ unsigned long long ffma2(
    unsigned long long a, unsigned long long bb, unsigned long long c)
{
    unsigned long long r;
    asm("fma.rn.f32x2 %0, %1, %2, %3;" : "=l"(r) : "l"(a), "l"(bb), "l"(c));
    return r;
}

#define NEG1X2 0xBF800000BF800000ull   // packed (-1.0f, -1.0f)

// Packed distance key: d_c = fma(a_c, -1, q_c) (== q-a, single rounding),
// s += d*d packed; combine even/odd partial sums, sqrt, return float bits.
__device__ __forceinline__ unsigned dist_key_p(const unsigned long long* qp,
                                               int b, int j)
{
    const ulonglong2* P0 = reinterpret_cast<const ulonglong2*>(T4g[b][0]);
    const ulonglong2* P1 = reinterpret_cast<const ulonglong2*>(T4g[b][1]);
    const ulonglong2* P2 = reinterpret_cast<const ulonglong2*>(T4g[b][2]);
    const ulonglong2* P3 = reinterpret_cast<const ulonglong2*>(T4g[b][3]);
    ulonglong2 a0 = P0[j], a1 = P1[j], a2 = P2[j], a3 = P3[j];

    unsigned long long s = 0ull, d;                 // packed (0.0, 0.0)
    d = ffma2(a0.x, NEG1X2, qp[0]); s = ffma2(d, d, s);
    d = ffma2(a0.y, NEG1X2, qp[1]); s = ffma2(d, d, s);
    d = ffma2(a1.x, NEG1X2, qp[2]); s = ffma2(d, d, s);
    d = ffma2(a1.y, NEG1X2, qp[3]); s = ffma2(d, d, s);
    d = ffma2(a2.x, NEG1X2, qp[4]); s = ffma2(d, d, s);
    d = ffma2(a2.y, NEG1X2, qp[5]); s = ffma2(d, d, s);
    d = ffma2(a3.x, NEG1X2, qp[6]); s = ffma2(d, d, s);
    d = ffma2(a3.y, NEG1X2, qp[7]); s = ffma2(d, d, s);

    unsigned lo, hi;
    asm("mov.b64 {%0, %1}, %2;" : "=r"(lo), "=r"(hi) : "l"(s));
    float sum = __uint_as_float(lo) + __uint_as_float(hi);
    return __float_as_uint(__fsqrt_rn(sum));        // compare post-sqrt
}

__device__ __forceinline__ unsigned long long umin64(unsigned long long a,
                                                     unsigned long long b)
{ return (b < a) ? b : a; }
__device__ __forceinline__ unsigned long long umax64(unsigned long long a,
                                                     unsigned long long b)
{ return (a < b) ? b : a; }

__global__ __launch_bounds__(THREADS, 9)
void knn_kernel(float2* __restrict__ out)
{
    __shared__ unsigned sD[WPC][KNN][32];            // fallback scratch (rare)
    __shared__ int      sJ[WPC][KNN][32];
    __shared__ unsigned long long sX[WPC][16];       // pair exchange

    const int b    = blockIdx.y;
    const int wid  = threadIdx.x >> 5;
    const int lane = threadIdx.x & 31;
    const int pair = wid >> 1;
    const int half = wid & 1;
    const int q    = blockIdx.x * 2 + pair;          // 0..2047
    const int jbase = half * (NPTS / 2);             // this warp's candidate half

    // Query point, packed pairs (dims 2i, 2i+1).
    unsigned long long qp[8];
    {
        const ulonglong2* P0 = reinterpret_cast<const ulonglong2*>(T4g[b][0]);
        const ulonglong2* P1 = reinterpret_cast<const ulonglong2*>(T4g[b][1]);
        const ulonglong2* P2 = reinterpret_cast<const ulonglong2*>(T4g[b][2]);
        const ulonglong2* P3 = reinterpret_cast<const ulonglong2*>(T4g[b][3]);
        ulonglong2 t;
        t = P0[q]; qp[0] = t.x; qp[1] = t.y;
        t = P1[q]; qp[2] = t.x; qp[3] = t.y;
        t = P2[q]; qp[4] = t.x; qp[5] = t.y;
        t = P3[q]; qp[6] = t.x; qp[7] = t.y;
    }

    // ---- Pass over 1024 candidates: per-lane sorted top-6 ----
    unsigned D[KL];
    int      J[KL];
#pragma unroll
    for (int i = 0; i < KL; ++i) { D[i] = 0xFFFFFFFFu; J[i] = 0x7FFFFFFF; }

#pragma unroll 2
    for (int t = 0; t < HALF_STEPS; ++t) {
        const int j = jbase + t * 32 + lane;
        unsigned kb = dist_key_p(qp, b, j);
        if (j == q) kb = 0xFFFFFFFFu;                // exclude self

        if (kb < D[KL - 1]) {                        // stable strict-<
            D[KL - 1] = kb; J[KL - 1] = j;
#pragma unroll
            for (int i = KL - 1; i > 0; --i) {
                if (D[i] < D[i - 1]) {
                    unsigned td = D[i]; D[i] = D[i - 1]; D[i - 1] = td;
                    int      tj = J[i]; J[i] = J[i - 1]; J[i - 1] = tj;
                }
            }
        }
    }

    // ---- 16-round warp-min pop merge; lane r captures round-r winner ----
    unsigned long long keep = 0xFFFFFFFFFFFFFFFFull;
    int cnt = 0;
    unsigned long long h = ((unsigned long long)D[0] << 32) | (unsigned)J[0];
#pragma unroll
    for (int r = 0; r < KNN; ++r) {
        unsigned long long v = h;
#pragma unroll
        for (int off = 16; off > 0; off >>= 1)
            v = umin64(v, __shfl_xor_sync(0xFFFFFFFFu, v, off));
        if (lane == r) keep = v;
        if (h == v) {                                // real keys unique
            ++cnt;
#pragma unroll
            for (int i = 0; i < KL - 1; ++i) { D[i] = D[i + 1]; J[i] = J[i + 1]; }
            D[KL - 1] = 0xFFFFFFFFu; J[KL - 1] = 0x7FFFFFFF;
            h = ((unsigned long long)D[0] << 32) | (unsigned)J[0];
        }
    }

    // ---- Guard: fully-popped lane may have discarded a needed 7th entry ----
    if (__ballot_sync(0xFFFFFFFFu, cnt == KL) != 0) {
#pragma unroll 1
        for (int i = 0; i < KNN; ++i) { sD[wid][i][lane] = 0xFFFFFFFFu; sJ[wid][i][lane] = 0x7FFFFFFF; }
#pragma unroll 1
        for (int t = 0; t < HALF_STEPS; ++t) {
            const int j = jbase + t * 32 + lane;
            unsigned kk = dist_key_p(qp, b, j);      // same bits as fast path
            if (j == q) continue;
            if (kk < sD[wid][KNN - 1][lane]) {
                int p = KNN - 1;
#pragma unroll 1
                while (p > 0 && kk < sD[wid][p - 1][lane]) {
                    sD[wid][p][lane] = sD[wid][p - 1][lane];
                    sJ[wid][p][lane] = sJ[wid][p - 1][lane];
                    --p;
                }
                sD[wid][p][lane] = kk; sJ[wid][p][lane] = j;
            }
        }
        int cur = 0;
        unsigned long long h2 = ((unsigned long long)sD[wid][0][lane] << 32)
                              | (unsigned)sJ[wid][0][lane];
#pragma unroll 1
        for (int r = 0; r < KNN; ++r) {
            unsigned long long v = h2;
#pragma unroll
            for (int off = 16; off > 0; off >>= 1)
                v = umin64(v, __shfl_xor_sync(0xFFFFFFFFu, v, off));
            if (lane == r) keep = v;
            if (h2 == v) {
                ++cur;
                h2 = (cur < KNN)
                   ? (((unsigned long long)sD[wid][cur][lane] << 32) | (unsigned)sJ[wid][cur][lane])
                   : 0xFFFFFFFFFFFFFFFFull;
            }
        }
    }

    // ---- Exchange + cross-half bitonic merge (even warp of each pair) ----
    if (lane < 16) sX[wid][lane] = keep;
    __syncthreads();

    if (half == 0) {
        // lanes 0..15: own ascending list; lanes 16..31: partner reversed.
        unsigned long long X = (lane < 16) ? keep : sX[wid + 1][31 - lane];
#pragma unroll
        for (int off = 16; off > 0; off >>= 1) {
            unsigned long long o = __shfl_xor_sync(0xFFFFFFFFu, X, off);
            X = (lane & off) ? umax64(X, o) : umin64(X, o);
        }
        if (lane < 16) {
            float2* outp = out + ((size_t)b * NPTS + q) * KNN;
            outp[lane] = make_float2((float)b,
                                     (float)(int)(unsigned)(X & 0xFFFFFFFFull));
        }
    }
}

extern "C" void kernel_launch(void* const* d_in, const int* in_sizes, int n_in,
                              void* d_out, int out_size)
{
    // points (2*2048*16) is the SMALLER input (features is 4x larger).
    const float* points;
    if (n_in >= 2) {
        points = (in_sizes[0] <= in_sizes[1]) ? (const float*)d_in[0]
                                              : (const float*)d_in[1];
    } else {
        points = (const float*)d_in[0];
    }

    transpose_kernel<<<(2 * 4 * NPTS + 255) / 256, 256>>>(points);

    dim3 grid(NPTS / 2, 2);          // 2 queries per CTA (4 warps), 2048 CTAs
    knn_kernel<<<grid, THREADS>>>((float2*)d_out);
}